// round 16
// baseline (speedup 1.0000x reference)
#include <cuda_runtime.h>
#include <cuda_fp16.h>
#include <cstdint>

// PointTransformerLayer, mma.sync.m16n8k16, 512 threads (16 warps).
// Tile = 128 rows = 8 pts x 16 nbrs. Warp tile = M32 x N32 (4 rowgrp x 2 colgrp
// per alpha/gamma side) -> B smem traffic halved vs M16xN64.
// A_ext[128x128] = [nf | delta]
// B: alpha n0-63 k0-63 = Wal ; gamma n64-127: k0-63 = -Wpsi@Wga, k64-127 = Wga
// fgc[8x64] = f@(Wphi@Wga)+cg per tile by alpha warps 0-3 (one extra MMA).
// gamma = acc + fgc ; alpha = acc + b_al + delta
// out[p,d] = sum_k softmax_d(gamma[k,:])[d] * alpha[k,d]
// Gamma softmax row-sums cross the 2 colgroups -> spart smem exchange.

constexpr int DIM = 64;
constexpr int THREADS = 512;
constexpr int LDA = 136;   // halves
constexpr int LDB = 136;   // halves
constexpr int LDF = 72;    // halves (f-tile / WfgB)
constexpr int LDW = 68;    // floats (ab) -- 272B stride, conflict-free

constexpr int AO     = 0;       // 34816  A_ext fp16 [128][136]
constexpr int BTO    = 34816;   // 34816  bt fp16 [128n][136k]
constexpr int FTO    = 69632;   // 2304   f16 f-tile [16][72]
constexpr int WFGO   = 71936;   // 9216   WfgB fp16 [64][72]
constexpr int FGCO   = 81152;   // 2048   fgc f32 [8][64]
constexpr int SPARTO = 83200;   // 1024   spart f32 [2][128]
constexpr int BALO   = 84224;   // 256
constexpr int CGSO   = 84480;   // 256
constexpr int MCVO   = 84736;   // 1024
constexpr int ABO    = 85760;   // 34816  ab f32 [128][68]
constexpr int RING0  = 120576;  // 2 x 36864
constexpr int SLOT   = 36864;
constexpr int RNF = 0;          // 32768
constexpr int RPF = 32768;      // 2048
constexpr int RPX = 34816;      // 128
constexpr int RNX = 34944;      // 1536
constexpr int SMEM_BYTES = RING0 + 2 * SLOT;  // 194304

__device__ __forceinline__ uint32_t s2u(const void* p) {
    uint32_t a;
    asm("{ .reg .u64 t; cvta.to.shared.u64 t, %1; cvt.u32.u64 %0, t; }" : "=r"(a) : "l"(p));
    return a;
}
__device__ __forceinline__ void cp16(unsigned dst, const void* src) {
    asm volatile("cp.async.cg.shared.global [%0], [%1], 16;\n" :: "r"(dst), "l"(src));
}
__device__ __forceinline__ void cp_commit() { asm volatile("cp.async.commit_group;\n"); }
template <int NN>
__device__ __forceinline__ void cp_wait() {
    asm volatile("cp.async.wait_group %0;\n" :: "n"(NN));
}
__device__ __forceinline__ void ldmx4(uint32_t* r, uint32_t addr) {
    asm volatile("ldmatrix.sync.aligned.m8n8.x4.shared.b16 {%0,%1,%2,%3}, [%4];"
                 : "=r"(r[0]), "=r"(r[1]), "=r"(r[2]), "=r"(r[3]) : "r"(addr));
}
__device__ __forceinline__ void mma16816(float* d, const uint32_t* a, const uint32_t* b) {
    asm volatile(
        "mma.sync.aligned.m16n8k16.row.col.f32.f16.f16.f32 "
        "{%0,%1,%2,%3}, {%4,%5,%6,%7}, {%8,%9}, {%0,%1,%2,%3};"
        : "+f"(d[0]), "+f"(d[1]), "+f"(d[2]), "+f"(d[3])
        : "r"(a[0]), "r"(a[1]), "r"(a[2]), "r"(a[3]), "r"(b[0]), "r"(b[1]));
}

__device__ __forceinline__ void prefetch_tile(char* slot, long tile, int tid,
                                              const float* __restrict__ pxyz,
                                              const float* __restrict__ nxyz,
                                              const float* __restrict__ nfeat,
                                              const float* __restrict__ pfeat)
{
    const long base = tile * 8;
    const unsigned nf_a = s2u(slot + RNF), pf_a = s2u(slot + RPF),
                   px_a = s2u(slot + RPX), nx_a = s2u(slot + RNX);
    const float* nsrc = nfeat + base * 1024;
    #pragma unroll
    for (int r = 0; r < 4; r++) { int i = tid + 512 * r; cp16(nf_a + i * 16, nsrc + i * 4); }
    if (tid < 128) cp16(pf_a + tid * 16, pfeat + base * 64 + tid * 4);
    if (tid < 6)   cp16(px_a + tid * 16, pxyz + base * 3 + tid * 4);
    if (tid < 96)  cp16(nx_a + tid * 16, nxyz + base * 48 + tid * 4);
    cp_commit();
}

__device__ __forceinline__ void convert_tile(char* sm, char* slot, int tid)
{
    const float4* rnf = (const float4*)(slot + RNF);
    __half* Ah = (__half*)(sm + AO);
    #pragma unroll
    for (int r = 0; r < 4; r++) {
        int i4 = tid + 512 * r;
        float4 v = rnf[i4];
        int e = i4 * 4, row = e >> 6, c = e & 63;
        __half2 h0 = __floats2half2_rn(v.x, v.y);
        __half2 h1 = __floats2half2_rn(v.z, v.w);
        *(uint2*)(Ah + row * LDA + c) = make_uint2(*(uint32_t*)&h0, *(uint32_t*)&h1);
    }
    if (tid < 256) {   // f16 f-tile [16][72] (rows 8..15 zero)
        __half* Fh = (__half*)(sm + FTO);
        const float4* rpf4 = (const float4*)(slot + RPF);
        int row = tid >> 4, q = tid & 15;
        float4 v = (row < 8) ? rpf4[row * 16 + q] : make_float4(0.f, 0.f, 0.f, 0.f);
        __half2 h0 = __floats2half2_rn(v.x, v.y);
        __half2 h1 = __floats2half2_rn(v.z, v.w);
        *(uint2*)(Fh + row * LDF + q * 4) = make_uint2(*(uint32_t*)&h0, *(uint32_t*)&h1);
    }
    {   // delta -> A cols 64..127
        const float* rpx = (const float*)(slot + RPX);
        const float* rnx = (const float*)(slot + RNX);
        const float* mcv = (const float*)(sm + MCVO);
        const int row = tid >> 2, q = tid & 3, p = row >> 4;
        const float dx = rpx[p * 3 + 0] - rnx[row * 3 + 0];
        const float dy = rpx[p * 3 + 1] - rnx[row * 3 + 1];
        const float dz = rpx[p * 3 + 2] - rnx[row * 3 + 2];
        #pragma unroll
        for (int i4 = 0; i4 < 4; i4++) {
            const int d = q * 16 + i4 * 4;
            float4 m0 = *(const float4*)(mcv + d);
            float4 m1 = *(const float4*)(mcv + 64 + d);
            float4 m2 = *(const float4*)(mcv + 128 + d);
            float4 cv = *(const float4*)(mcv + 192 + d);
            float v0 = fmaxf(fmaf(dx, m0.x, fmaf(dy, m1.x, fmaf(dz, m2.x, cv.x))), 0.f);
            float v1 = fmaxf(fmaf(dx, m0.y, fmaf(dy, m1.y, fmaf(dz, m2.y, cv.y))), 0.f);
            float v2 = fmaxf(fmaf(dx, m0.z, fmaf(dy, m1.z, fmaf(dz, m2.z, cv.z))), 0.f);
            float v3 = fmaxf(fmaf(dx, m0.w, fmaf(dy, m1.w, fmaf(dz, m2.w, cv.w))), 0.f);
            __half2 h0 = __floats2half2_rn(v0, v1);
            __half2 h1 = __floats2half2_rn(v2, v3);
            *(uint2*)(Ah + row * LDA + 64 + d) = make_uint2(*(uint32_t*)&h0, *(uint32_t*)&h1);
        }
    }
}

__global__ void __launch_bounds__(THREADS, 1)
pt_main(const float* __restrict__ pxyz,  const float* __restrict__ pfeat,
        const float* __restrict__ nxyz,  const float* __restrict__ nfeat,
        const float* __restrict__ Wphi,  const float* __restrict__ bphi,
        const float* __restrict__ Wpsi,  const float* __restrict__ bpsi,
        const float* __restrict__ Wal,   const float* __restrict__ bal,
        const float* __restrict__ Wga,   const float* __restrict__ bga,
        const float* __restrict__ Wd1,   const float* __restrict__ bd1,
        const float* __restrict__ Wd2,   const float* __restrict__ bd2,
        float* __restrict__ out, int N)
{
    extern __shared__ __align__(1024) char sm[];
    const int tid = threadIdx.x, lane = tid & 31, warp = tid >> 5;
    const int cg = warp >> 3;            // 0: alpha, 1: gamma (2+2 per SMSP)
    const int idx = warp & 7, rgrp = idx >> 1, cgrp = idx & 1;
    const int bx = blockIdx.x, G = gridDim.x;
    const int ntiles = (N + 7) >> 3;

    __half* bt = (__half*)(sm + BTO);

    // ---- Phase A: weight fusion (scratch overlays ring) ----
    {
        float* sWga  = (float*)(sm + RING0);
        float* sWgaT = (float*)(sm + RING0 + 16384);   // [64][68]
        float* sWphi = (float*)(sm + RING0 + 33792);
        float* sWpsi = (float*)(sm + RING0 + 50176);
        __half* wfg16 = (__half*)(sm + WFGO);
        #pragma unroll
        for (int m = 0; m < 8; m++) {
            int i = tid + 512 * m;
            sWga[i] = Wga[i]; sWphi[i] = Wphi[i]; sWpsi[i] = Wpsi[i];
        }
        __syncthreads();
        #pragma unroll
        for (int m = 0; m < 8; m++) {
            int i = tid + 512 * m; int e = i >> 6, d = i & 63;
            sWgaT[d * 68 + e] = sWga[e * 64 + d];
        }
        __syncthreads();
        #pragma unroll
        for (int m = 0; m < 8; m++) {
            int v = tid + 512 * m; int k = v >> 6, n = v & 63;
            bt[n * LDB + k]             = __float2half_rn(Wal[k * 64 + n]);
            bt[(64 + n) * LDB + 64 + k] = __float2half_rn(sWga[k * 64 + n]);
        }
        #pragma unroll
        for (int m = 0; m < 8; m++) {
            int v = tid + 512 * m; int k = v >> 6, n = v & 63;
            const float4* pa = (const float4*)(sWpsi + k * 64);
            const float4* pb = (const float4*)(sWphi + k * 64);
            const float4* pg = (const float4*)(sWgaT + n * 68);
            float s1 = 0.f, s2 = 0.f;
            #pragma unroll
            for (int e4 = 0; e4 < 16; e4++) {
                float4 a = pa[e4], bb = pb[e4], g = pg[e4];
                s1 = fmaf(a.x, g.x, fmaf(a.y, g.y, fmaf(a.z, g.z, fmaf(a.w, g.w, s1))));
                s2 = fmaf(bb.x, g.x, fmaf(bb.y, g.y, fmaf(bb.z, g.z, fmaf(bb.w, g.w, s2))));
            }
            bt[(64 + n) * LDB + k] = __float2half_rn(-s1);  // -Wpsi@Wga
            wfg16[n * LDF + k]     = __float2half_rn(s2);   //  Wphi@Wga
        }
        if (tid < 64) {
            float s = bga[tid];
            const float* gt = sWgaT + tid * 68;
            for (int e = 0; e < 64; e++) s = fmaf(bphi[e] - bpsi[e], gt[e], s);
            ((float*)(sm + CGSO))[tid] = s;
        }
        if (tid < 256) {
            int r = tid >> 6, d = tid & 63;
            float s;
            if (r < 3) {
                s = 0.f;
                for (int c = 0; c < 64; c++) s = fmaf(Wd1[r * 64 + c], Wd2[c * 64 + d], s);
            } else {
                s = bd2[d];
                for (int c = 0; c < 64; c++) s = fmaf(bd1[c], Wd2[c * 64 + d], s);
            }
            ((float*)(sm + MCVO))[tid] = s;
        }
        if (tid < 64) ((float*)(sm + BALO))[tid] = bal[tid];
        __syncthreads();
    }

    // ---- loop-invariant operand addresses ----
    const uint32_t smA32 = s2u(sm + AO), smB32 = s2u(sm + BTO);
    const int row0 = rgrp * 32;
    const uint32_t abase =
        smA32 + (uint32_t)(((row0 + (lane & 15)) * LDA + (lane >> 4) * 8) * 2);
    uint32_t bb2[2];
    {
        const int m = lane >> 3;
        const int nrow = cg * 64 + cgrp * 32 + (m >> 1) * 8 + (lane & 7);
        #pragma unroll
        for (int n4 = 0; n4 < 2; n4++)
            bb2[n4] = smB32 + (uint32_t)(((nrow + n4 * 16) * LDB + (m & 1) * 8) * 2);
    }
    uint32_t fa = 0, fb = 0;
    if (!cg && idx < 4) {
        const int m = lane >> 3;
        fa = s2u(sm + FTO) + (uint32_t)(((lane & 15) * LDF + (lane >> 4) * 8) * 2);
        fb = s2u(sm + WFGO) +
             (uint32_t)(((idx * 16 + (m >> 1) * 8 + (lane & 7)) * LDF + (m & 1) * 8) * 2);
    }
    float* ab = (float*)(sm + ABO);
    float* spart = (float*)(sm + SPARTO);
    const float* balv = (const float*)(sm + BALO);
    const float* fgcs = (const float*)(sm + FGCO);
    const __half* Ah  = (const __half*)(sm + AO);

    // ---- prime 2-slot ring ----
    #pragma unroll
    for (int s = 0; s < 2; s++) {
        long tt = (long)bx + (long)s * G;
        if (tt < ntiles) prefetch_tile(sm + RING0 + s * SLOT, tt, tid, pxyz, nxyz, nfeat, pfeat);
        else cp_commit();
    }

    int sl = 0;
    for (long t = bx; t < ntiles; t += G) {
        cp_wait<1>();
        __syncthreads();
        convert_tile(sm, sm + RING0 + sl * SLOT, tid);
        __syncthreads();
        if (t + 2L * G < ntiles)
            prefetch_tile(sm + RING0 + sl * SLOT, t + 2L * G, tid, pxyz, nxyz, nfeat, pfeat);
        else
            cp_commit();

        float acc[2][4][4];
        #pragma unroll
        for (int mg = 0; mg < 2; mg++)
            #pragma unroll
            for (int n8 = 0; n8 < 4; n8++)
                acc[mg][n8][0] = acc[mg][n8][1] = acc[mg][n8][2] = acc[mg][n8][3] = 0.f;

        const int nkk = cg ? 8 : 4;
        for (int kk = 0; kk < nkk; kk++) {
            uint32_t b0[4], b1[4];
            ldmx4(b0, bb2[0] + kk * 32);
            ldmx4(b1, bb2[1] + kk * 32);
            #pragma unroll
            for (int mg = 0; mg < 2; mg++) {
                uint32_t a[4];
                ldmx4(a, abase + (uint32_t)(mg * 16 * LDA * 2) + kk * 32);
                mma16816(acc[mg][0], a, b0);
                mma16816(acc[mg][1], a, b0 + 2);
                mma16816(acc[mg][2], a, b1);
                mma16816(acc[mg][3], a, b1 + 2);
            }
        }

        if (!cg) {
            // alpha -> ab (cols cgrp*32..+32)
            #pragma unroll
            for (int mg = 0; mg < 2; mg++) {
                const int rl = row0 + mg * 16 + (lane >> 2);
                #pragma unroll
                for (int n8 = 0; n8 < 4; n8++) {
                    const int d0 = cgrp * 32 + n8 * 8 + 2 * (lane & 3);
                    float2 bl = *(const float2*)(balv + d0);
                    __half2 dl = *(const __half2*)(Ah + rl * LDA + 64 + d0);
                    __half2 dh = *(const __half2*)(Ah + (rl + 8) * LDA + 64 + d0);
                    float2 dlo = __half22float2(dl), dhi = __half22float2(dh);
                    *(float2*)(ab + rl * LDW + d0) =
                        make_float2(acc[mg][n8][0] + bl.x + dlo.x, acc[mg][n8][1] + bl.y + dlo.y);
                    *(float2*)(ab + (rl + 8) * LDW + d0) =
                        make_float2(acc[mg][n8][2] + bl.x + dhi.x, acc[mg][n8][3] + bl.y + dhi.y);
                }
            }
            // fgc MMA (warps 0-3): fgc[8][64] = f@Wfg + cg
            if (idx < 4) {
                float f0[4] = {0.f, 0.f, 0.f, 0.f}, f1[4] = {0.f, 0.f, 0.f, 0.f};
                #pragma unroll
                for (int kk = 0; kk < 4; kk++) {
                    uint32_t a[4], b[4];
                    ldmx4(a, fa + kk * 32);
                    ldmx4(b, fb + kk * 32);
                    mma16816(f0, a, b);
                    mma16816(f1, a, b + 2);
                }
                float* fgc = (float*)(sm + FGCO);
                const float* cgvv = (const float*)(sm + CGSO);
                const int prow = lane >> 2;
                const int dd = idx * 16 + 2 * (lane & 3);
                float2 c0 = *(const float2*)(cgvv + dd);
                float2 c1 = *(const float2*)(cgvv + dd + 8);
                *(float2*)(fgc + prow * 64 + dd)     = make_float2(f0[0] + c0.x, f0[1] + c0.y);
                *(float2*)(fgc + prow * 64 + dd + 8) = make_float2(f1[0] + c1.x, f1[1] + c1.y);
            }
        }
        __syncthreads();

        float slm[2], shm[2];
        if (cg) {
            // gamma: add fgc, exp, partial sums over this colgroup's 32 dims
            #pragma unroll
            for (int mg = 0; mg < 2; mg++) {
                const int p0 = rgrp * 2 + mg;
                float slo = 0.f, shi = 0.f;
                #pragma unroll
                for (int n8 = 0; n8 < 4; n8++) {
                    const int d0 = cgrp * 32 + n8 * 8 + 2 * (lane & 3);
                    float2 fg = *(const float2*)(fgcs + p0 * 64 + d0);
                    acc[mg][n8][0] = __expf(acc[mg][n8][0] + fg.x);
                    acc[mg][n8][1] = __expf(acc[mg][n8][1] + fg.y);
                    acc[mg][n8][2] = __expf(acc[mg][n8][2] + fg.x);
                    acc[mg][n8][3] = __expf(acc[mg][n8][3] + fg.y);
                    slo += acc[mg][n8][0] + acc[mg][n8][1];
                    shi += acc[mg][n8][2] + acc[mg][n8][3];
                }
                slo += __shfl_xor_sync(0xffffffffu, slo, 1);
                slo += __shfl_xor_sync(0xffffffffu, slo, 2);
                shi += __shfl_xor_sync(0xffffffffu, shi, 1);
                shi += __shfl_xor_sync(0xffffffffu, shi, 2);
                slm[mg] = slo; shm[mg] = shi;
                if ((lane & 3) == 0) {
                    const int r = p0 * 16 + (lane >> 2);
                    spart[cgrp * 128 + r]     = slo;
                    spart[cgrp * 128 + r + 8] = shi;
                }
            }
        }
        __syncthreads();

        if (cg) {
            const int oc = (cgrp ^ 1) * 128;
            #pragma unroll
            for (int mg = 0; mg < 2; mg++) {
                const int p0 = rgrp * 2 + mg;
                const long gp = t * 8 + p0;
                const int rl = p0 * 16 + (lane >> 2);
                const float il = __fdividef(1.f, slm[mg] + spart[oc + rl]);
                const float ih = __fdividef(1.f, shm[mg] + spart[oc + rl + 8]);
                #pragma unroll
                for (int n8 = 0; n8 < 4; n8++) {
                    const int d0 = cgrp * 32 + n8 * 8 + 2 * (lane & 3);
                    float2 a0 = *(const float2*)(ab + rl * LDW + d0);
                    float2 a1 = *(const float2*)(ab + (rl + 8) * LDW + d0);
                    float sx = acc[mg][n8][0] * il * a0.x + acc[mg][n8][2] * ih * a1.x;
                    float sy = acc[mg][n8][1] * il * a0.y + acc[mg][n8][3] * ih * a1.y;
                    sx += __shfl_xor_sync(0xffffffffu, sx, 4);
                    sx += __shfl_xor_sync(0xffffffffu, sx, 8);
                    sx += __shfl_xor_sync(0xffffffffu, sx, 16);
                    sy += __shfl_xor_sync(0xffffffffu, sy, 4);
                    sy += __shfl_xor_sync(0xffffffffu, sy, 8);
                    sy += __shfl_xor_sync(0xffffffffu, sy, 16);
                    if ((lane >> 2) == n8 && gp < N)
                        *(float2*)(out + gp * 64 + d0) = make_float2(sx, sy);
                }
            }
        }
        sl ^= 1;
    }
}

extern "C" void kernel_launch(void* const* d_in, const int* in_sizes, int n_in,
                              void* d_out, int out_size)
{
    const float* pxyz  = (const float*)d_in[0];
    const float* pfeat = (const float*)d_in[1];
    const float* nxyz  = (const float*)d_in[2];
    const float* nfeat = (const float*)d_in[3];
    const float* Wphi  = (const float*)d_in[4];
    const float* bphi  = (const float*)d_in[5];
    const float* Wpsi  = (const float*)d_in[6];
    const float* bpsi  = (const float*)d_in[7];
    const float* Wal   = (const float*)d_in[8];
    const float* bal   = (const float*)d_in[9];
    const float* Wga   = (const float*)d_in[10];
    const float* bga   = (const float*)d_in[11];
    const float* Wd1   = (const float*)d_in[12];
    const float* bd1   = (const float*)d_in[13];
    const float* Wd2   = (const float*)d_in[14];
    const float* bd2   = (const float*)d_in[15];

    const int N = in_sizes[1] / DIM;

    int dev = 0;
    cudaGetDevice(&dev);
    int nsm = 148;
    cudaDeviceGetAttribute(&nsm, cudaDevAttrMultiProcessorCount, dev);

    cudaFuncSetAttribute(pt_main, cudaFuncAttributeMaxDynamicSharedMemorySize, SMEM_BYTES);

    const int ntiles = (N + 7) >> 3;
    const int grid = (ntiles < nsm) ? ntiles : nsm;
    pt_main<<<grid, THREADS, SMEM_BYTES>>>(pxyz, pfeat, nxyz, nfeat,
                                           Wphi, bphi, Wpsi, bpsi, Wal, bal,
                                           Wga, bga, Wd1, bd1, Wd2, bd2,
                                           (float*)d_out, N);
}

// round 17
// speedup vs baseline: 1.6009x; 1.6009x over previous
#include <cuda_runtime.h>
#include <cuda_fp16.h>
#include <cstdint>

// PointTransformerLayer, mma.sync.m16n8k16, 512 threads (16 warps).
// Tile = 128 rows = 8 pts x 16 nbrs; warp owns 16 rows (1 pt).  [R15 layout]
// A_ext[128x128] = [nf | delta]
// B: alpha n0-63 k0-63 = Wal ; gamma n64-127: k0-63 = -Wpsi@Wga, k64-127 = Wga
// fgc[8x64] = f@(Wphi@Wga)+cg per tile by alpha warps 0-3 (one extra MMA).
// gamma = acc + fgc ; alpha = acc + b_al + delta
// out[p,d] = sum_k softmax_d(gamma[k,:])[d] * alpha[k,d]
// R16 change: kk loops are compile-time unrolled (cg split) for LDS batching.

constexpr int DIM = 64;
constexpr int THREADS = 512;
constexpr int LDA = 136;   // halves, A row
constexpr int LDB = 136;   // halves, B row
constexpr int LDF = 72;    // halves, WfgB / f-tile row
constexpr int LDW = 72;    // floats, ab

constexpr int AO    = 0;       // 34816  A_ext fp16 [128][136]
constexpr int BTO   = 34816;   // 34816  bt fp16 [128n][136k]
constexpr int FTO   = 69632;   // 2304   f16 f-tile [16][72]
constexpr int WFGO  = 71936;   // 9216   WfgB fp16 [64n(d)][72k(c)]
constexpr int FGCO  = 81152;   // 2048   fgc f32 [8][64]
constexpr int BALO  = 83200;   // 256
constexpr int CGSO  = 83456;   // 256
constexpr int MCVO  = 83712;   // 1024
constexpr int ABO   = 84736;   // 36864  ab f32 [128][72]
constexpr int RING0 = 121600;  // 2 x 36864 (phase-A scratch overlays)
constexpr int SLOT  = 36864;
constexpr int RNF = 0;         // 32768
constexpr int RPF = 32768;     // 2048
constexpr int RPX = 34816;     // 128
constexpr int RNX = 34944;     // 1536
constexpr int SMEM_BYTES = RING0 + 2 * SLOT;  // 195328

__device__ __forceinline__ uint32_t s2u(const void* p) {
    uint32_t a;
    asm("{ .reg .u64 t; cvta.to.shared.u64 t, %1; cvt.u32.u64 %0, t; }" : "=r"(a) : "l"(p));
    return a;
}
__device__ __forceinline__ void cp16(unsigned dst, const void* src) {
    asm volatile("cp.async.cg.shared.global [%0], [%1], 16;\n" :: "r"(dst), "l"(src));
}
__device__ __forceinline__ void cp_commit() { asm volatile("cp.async.commit_group;\n"); }
template <int NN>
__device__ __forceinline__ void cp_wait() {
    asm volatile("cp.async.wait_group %0;\n" :: "n"(NN));
}
__device__ __forceinline__ void ldmx4(uint32_t* r, uint32_t addr) {
    asm volatile("ldmatrix.sync.aligned.m8n8.x4.shared.b16 {%0,%1,%2,%3}, [%4];"
                 : "=r"(r[0]), "=r"(r[1]), "=r"(r[2]), "=r"(r[3]) : "r"(addr));
}
__device__ __forceinline__ void mma16816(float* d, const uint32_t* a, const uint32_t* b) {
    asm volatile(
        "mma.sync.aligned.m16n8k16.row.col.f32.f16.f16.f32 "
        "{%0,%1,%2,%3}, {%4,%5,%6,%7}, {%8,%9}, {%0,%1,%2,%3};"
        : "+f"(d[0]), "+f"(d[1]), "+f"(d[2]), "+f"(d[3])
        : "r"(a[0]), "r"(a[1]), "r"(a[2]), "r"(a[3]), "r"(b[0]), "r"(b[1]));
}

__device__ __forceinline__ void prefetch_tile(char* slot, long tile, int tid,
                                              const float* __restrict__ pxyz,
                                              const float* __restrict__ nxyz,
                                              const float* __restrict__ nfeat,
                                              const float* __restrict__ pfeat)
{
    const long base = tile * 8;
    const unsigned nf_a = s2u(slot + RNF), pf_a = s2u(slot + RPF),
                   px_a = s2u(slot + RPX), nx_a = s2u(slot + RNX);
    const float* nsrc = nfeat + base * 1024;
    #pragma unroll
    for (int r = 0; r < 4; r++) { int i = tid + 512 * r; cp16(nf_a + i * 16, nsrc + i * 4); }
    if (tid < 128) cp16(pf_a + tid * 16, pfeat + base * 64 + tid * 4);
    if (tid < 6)   cp16(px_a + tid * 16, pxyz + base * 3 + tid * 4);
    if (tid < 96)  cp16(nx_a + tid * 16, nxyz + base * 48 + tid * 4);
    cp_commit();
}

__device__ __forceinline__ void convert_tile(char* sm, char* slot, int tid)
{
    const float4* rnf = (const float4*)(slot + RNF);
    __half* Ah = (__half*)(sm + AO);
    #pragma unroll
    for (int r = 0; r < 4; r++) {
        int i4 = tid + 512 * r;
        float4 v = rnf[i4];
        int e = i4 * 4, row = e >> 6, c = e & 63;
        __half2 h0 = __floats2half2_rn(v.x, v.y);
        __half2 h1 = __floats2half2_rn(v.z, v.w);
        *(uint2*)(Ah + row * LDA + c) = make_uint2(*(uint32_t*)&h0, *(uint32_t*)&h1);
    }
    if (tid < 256) {   // f16 f-tile [16][72] (rows 8..15 zero)
        __half* Fh = (__half*)(sm + FTO);
        const float4* rpf4 = (const float4*)(slot + RPF);
        int row = tid >> 4, q = tid & 15;
        float4 v = (row < 8) ? rpf4[row * 16 + q] : make_float4(0.f, 0.f, 0.f, 0.f);
        __half2 h0 = __floats2half2_rn(v.x, v.y);
        __half2 h1 = __floats2half2_rn(v.z, v.w);
        *(uint2*)(Fh + row * LDF + q * 4) = make_uint2(*(uint32_t*)&h0, *(uint32_t*)&h1);
    }
    {   // delta -> A cols 64..127
        const float* rpx = (const float*)(slot + RPX);
        const float* rnx = (const float*)(slot + RNX);
        const float* mcv = (const float*)(sm + MCVO);
        const int row = tid >> 2, q = tid & 3, p = row >> 4;
        const float dx = rpx[p * 3 + 0] - rnx[row * 3 + 0];
        const float dy = rpx[p * 3 + 1] - rnx[row * 3 + 1];
        const float dz = rpx[p * 3 + 2] - rnx[row * 3 + 2];
        #pragma unroll
        for (int i4 = 0; i4 < 4; i4++) {
            const int d = q * 16 + i4 * 4;
            float4 m0 = *(const float4*)(mcv + d);
            float4 m1 = *(const float4*)(mcv + 64 + d);
            float4 m2 = *(const float4*)(mcv + 128 + d);
            float4 cv = *(const float4*)(mcv + 192 + d);
            float v0 = fmaxf(fmaf(dx, m0.x, fmaf(dy, m1.x, fmaf(dz, m2.x, cv.x))), 0.f);
            float v1 = fmaxf(fmaf(dx, m0.y, fmaf(dy, m1.y, fmaf(dz, m2.y, cv.y))), 0.f);
            float v2 = fmaxf(fmaf(dx, m0.z, fmaf(dy, m1.z, fmaf(dz, m2.z, cv.z))), 0.f);
            float v3 = fmaxf(fmaf(dx, m0.w, fmaf(dy, m1.w, fmaf(dz, m2.w, cv.w))), 0.f);
            __half2 h0 = __floats2half2_rn(v0, v1);
            __half2 h1 = __floats2half2_rn(v2, v3);
            *(uint2*)(Ah + row * LDA + 64 + d) = make_uint2(*(uint32_t*)&h0, *(uint32_t*)&h1);
        }
    }
}

__global__ void __launch_bounds__(THREADS, 1)
pt_main(const float* __restrict__ pxyz,  const float* __restrict__ pfeat,
        const float* __restrict__ nxyz,  const float* __restrict__ nfeat,
        const float* __restrict__ Wphi,  const float* __restrict__ bphi,
        const float* __restrict__ Wpsi,  const float* __restrict__ bpsi,
        const float* __restrict__ Wal,   const float* __restrict__ bal,
        const float* __restrict__ Wga,   const float* __restrict__ bga,
        const float* __restrict__ Wd1,   const float* __restrict__ bd1,
        const float* __restrict__ Wd2,   const float* __restrict__ bd2,
        float* __restrict__ out, int N)
{
    extern __shared__ __align__(1024) char sm[];
    const int tid = threadIdx.x, lane = tid & 31, warp = tid >> 5;
    const int cg = warp >> 3, rw = warp & 7;   // SMSP = warp&3: 2 alpha + 2 gamma each
    const int bx = blockIdx.x, G = gridDim.x;
    const int ntiles = (N + 7) >> 3;

    __half* bt = (__half*)(sm + BTO);

    // ---- Phase A: weight fusion (scratch overlays ring) ----
    {
        float* sWga  = (float*)(sm + RING0);
        float* sWgaT = (float*)(sm + RING0 + 16384);   // [64][68]
        float* sWphi = (float*)(sm + RING0 + 33792);
        float* sWpsi = (float*)(sm + RING0 + 50176);
        __half* wfg16 = (__half*)(sm + WFGO);
        #pragma unroll
        for (int m = 0; m < 8; m++) {
            int i = tid + 512 * m;
            sWga[i] = Wga[i]; sWphi[i] = Wphi[i]; sWpsi[i] = Wpsi[i];
        }
        __syncthreads();
        #pragma unroll
        for (int m = 0; m < 8; m++) {
            int i = tid + 512 * m; int e = i >> 6, d = i & 63;
            sWgaT[d * 68 + e] = sWga[e * 64 + d];
        }
        __syncthreads();
        #pragma unroll
        for (int m = 0; m < 8; m++) {
            int v = tid + 512 * m; int k = v >> 6, n = v & 63;
            bt[n * LDB + k]             = __float2half_rn(Wal[k * 64 + n]);
            bt[(64 + n) * LDB + 64 + k] = __float2half_rn(sWga[k * 64 + n]);
        }
        #pragma unroll
        for (int m = 0; m < 8; m++) {
            int v = tid + 512 * m; int k = v >> 6, n = v & 63;
            const float4* pa = (const float4*)(sWpsi + k * 64);
            const float4* pb = (const float4*)(sWphi + k * 64);
            const float4* pg = (const float4*)(sWgaT + n * 68);
            float s1 = 0.f, s2 = 0.f;
            #pragma unroll
            for (int e4 = 0; e4 < 16; e4++) {
                float4 a = pa[e4], bb = pb[e4], g = pg[e4];
                s1 = fmaf(a.x, g.x, fmaf(a.y, g.y, fmaf(a.z, g.z, fmaf(a.w, g.w, s1))));
                s2 = fmaf(bb.x, g.x, fmaf(bb.y, g.y, fmaf(bb.z, g.z, fmaf(bb.w, g.w, s2))));
            }
            bt[(64 + n) * LDB + k] = __float2half_rn(-s1);  // -Wpsi@Wga
            wfg16[n * LDF + k]     = __float2half_rn(s2);   //  Wphi@Wga
        }
        if (tid < 64) {
            float s = bga[tid];
            const float* gt = sWgaT + tid * 68;
            for (int e = 0; e < 64; e++) s = fmaf(bphi[e] - bpsi[e], gt[e], s);
            ((float*)(sm + CGSO))[tid] = s;
        }
        if (tid < 256) {
            int r = tid >> 6, d = tid & 63;
            float s;
            if (r < 3) {
                s = 0.f;
                for (int c = 0; c < 64; c++) s = fmaf(Wd1[r * 64 + c], Wd2[c * 64 + d], s);
            } else {
                s = bd2[d];
                for (int c = 0; c < 64; c++) s = fmaf(bd1[c], Wd2[c * 64 + d], s);
            }
            ((float*)(sm + MCVO))[tid] = s;
        }
        if (tid < 64) ((float*)(sm + BALO))[tid] = bal[tid];
        __syncthreads();
    }

    // ---- loop-invariant operand addresses ----
    const uint32_t smA32 = s2u(sm + AO), smB32 = s2u(sm + BTO);
    const int row0 = rw * 16, p = rw;
    const uint32_t abase =
        smA32 + (uint32_t)(((row0 + (lane & 15)) * LDA + (lane >> 4) * 8) * 2);
    uint32_t bb4[4];
    {
        const int m = lane >> 3;
        const int nrow = cg * 64 + (m >> 1) * 8 + (lane & 7);
        #pragma unroll
        for (int n4 = 0; n4 < 4; n4++)
            bb4[n4] = smB32 + (uint32_t)(((nrow + n4 * 16) * LDB + (m & 1) * 8) * 2);
    }
    // fgc MMA addresses (alpha warps 0-3)
    uint32_t fa = 0, fb = 0;
    if (!cg && rw < 4) {
        const int m = lane >> 3;
        fa = s2u(sm + FTO) + (uint32_t)(((lane & 15) * LDF + (lane >> 4) * 8) * 2);
        fb = s2u(sm + WFGO) +
             (uint32_t)(((rw * 16 + (m >> 1) * 8 + (lane & 7)) * LDF + (m & 1) * 8) * 2);
    }
    float* ab = (float*)(sm + ABO);
    const float* balv = (const float*)(sm + BALO);
    const float* fgcs = (const float*)(sm + FGCO);
    const __half* Ah  = (const __half*)(sm + AO);
    const int rl = p * 16 + (lane >> 2);

    // ---- prime 2-slot ring ----
    #pragma unroll
    for (int s = 0; s < 2; s++) {
        long tt = (long)bx + (long)s * G;
        if (tt < ntiles) prefetch_tile(sm + RING0 + s * SLOT, tt, tid, pxyz, nxyz, nfeat, pfeat);
        else cp_commit();
    }

    int sl = 0;
    for (long t = bx; t < ntiles; t += G) {
        cp_wait<1>();
        __syncthreads();
        convert_tile(sm, sm + RING0 + sl * SLOT, tid);
        __syncthreads();
        if (t + 2L * G < ntiles)
            prefetch_tile(sm + RING0 + sl * SLOT, t + 2L * G, tid, pxyz, nxyz, nfeat, pfeat);
        else
            cp_commit();

        float acc[8][4];
        #pragma unroll
        for (int n8 = 0; n8 < 8; n8++)
            acc[n8][0] = acc[n8][1] = acc[n8][2] = acc[n8][3] = 0.f;

        // compile-time-unrolled MMA loops (lets ptxas batch LDS, interleave MMA)
        if (cg) {
            #pragma unroll
            for (int kk = 0; kk < 8; kk++) {
                uint32_t a[4];
                ldmx4(a, abase + kk * 32);
                #pragma unroll
                for (int n4 = 0; n4 < 4; n4++) {
                    uint32_t b[4];
                    ldmx4(b, bb4[n4] + kk * 32);
                    mma16816(acc[2 * n4],     a, b);
                    mma16816(acc[2 * n4 + 1], a, b + 2);
                }
            }
        } else {
            #pragma unroll
            for (int kk = 0; kk < 4; kk++) {
                uint32_t a[4];
                ldmx4(a, abase + kk * 32);
                #pragma unroll
                for (int n4 = 0; n4 < 4; n4++) {
                    uint32_t b[4];
                    ldmx4(b, bb4[n4] + kk * 32);
                    mma16816(acc[2 * n4],     a, b);
                    mma16816(acc[2 * n4 + 1], a, b + 2);
                }
            }
        }

        if (!cg) {
            // alpha -> smem
            #pragma unroll
            for (int n8 = 0; n8 < 8; n8++) {
                const int d0 = n8 * 8 + 2 * (lane & 3);
                float2 bl = *(const float2*)(balv + d0);
                __half2 dl = *(const __half2*)(Ah + rl * LDA + 64 + d0);
                __half2 dh = *(const __half2*)(Ah + (rl + 8) * LDA + 64 + d0);
                float2 dlo = __half22float2(dl), dhi = __half22float2(dh);
                *(float2*)(ab + rl * LDW + d0) =
                    make_float2(acc[n8][0] + bl.x + dlo.x, acc[n8][1] + bl.y + dlo.y);
                *(float2*)(ab + (rl + 8) * LDW + d0) =
                    make_float2(acc[n8][2] + bl.x + dhi.x, acc[n8][3] + bl.y + dhi.y);
            }
            // fgc MMA (warps 0-3): fgc[8][64] = f@Wfg + cg
            if (rw < 4) {
                float f0[4] = {0.f, 0.f, 0.f, 0.f}, f1[4] = {0.f, 0.f, 0.f, 0.f};
                #pragma unroll
                for (int kk = 0; kk < 4; kk++) {
                    uint32_t a[4], b[4];
                    ldmx4(a, fa + kk * 32);
                    ldmx4(b, fb + kk * 32);
                    mma16816(f0, a, b);
                    mma16816(f1, a, b + 2);
                }
                float* fgc = (float*)(sm + FGCO);
                const float* cgvv = (const float*)(sm + CGSO);
                const int prow = lane >> 2;
                const int dd = rw * 16 + 2 * (lane & 3);
                float2 c0 = *(const float2*)(cgvv + dd);
                float2 c1 = *(const float2*)(cgvv + dd + 8);
                *(float2*)(fgc + prow * 64 + dd)     = make_float2(f0[0] + c0.x, f0[1] + c0.y);
                *(float2*)(fgc + prow * 64 + dd + 8) = make_float2(f1[0] + c1.x, f1[1] + c1.y);
            }
        }
        __syncthreads();

        if (cg) {
            // gamma: add fgc, softmax on registers, w*alpha reduce, write out
            float slo = 0.f, shi = 0.f;
            #pragma unroll
            for (int n8 = 0; n8 < 8; n8++) {
                const int d0 = n8 * 8 + 2 * (lane & 3);
                float2 fg = *(const float2*)(fgcs + p * 64 + d0);
                acc[n8][0] = __expf(acc[n8][0] + fg.x);
                acc[n8][1] = __expf(acc[n8][1] + fg.y);
                acc[n8][2] = __expf(acc[n8][2] + fg.x);
                acc[n8][3] = __expf(acc[n8][3] + fg.y);
                slo += acc[n8][0] + acc[n8][1];
                shi += acc[n8][2] + acc[n8][3];
            }
            slo += __shfl_xor_sync(0xffffffffu, slo, 1);
            slo += __shfl_xor_sync(0xffffffffu, slo, 2);
            shi += __shfl_xor_sync(0xffffffffu, shi, 1);
            shi += __shfl_xor_sync(0xffffffffu, shi, 2);
            const float il = __fdividef(1.f, slo), ih = __fdividef(1.f, shi);
            const long gp = t * 8 + p;
            #pragma unroll
            for (int n8 = 0; n8 < 8; n8++) {
                const int d0 = n8 * 8 + 2 * (lane & 3);
                float2 a0 = *(const float2*)(ab + rl * LDW + d0);
                float2 a1 = *(const float2*)(ab + (rl + 8) * LDW + d0);
                float sx = acc[n8][0] * il * a0.x + acc[n8][2] * ih * a1.x;
                float sy = acc[n8][1] * il * a0.y + acc[n8][3] * ih * a1.y;
                sx += __shfl_xor_sync(0xffffffffu, sx, 4);
                sx += __shfl_xor_sync(0xffffffffu, sx, 8);
                sx += __shfl_xor_sync(0xffffffffu, sx, 16);
                sy += __shfl_xor_sync(0xffffffffu, sy, 4);
                sy += __shfl_xor_sync(0xffffffffu, sy, 8);
                sy += __shfl_xor_sync(0xffffffffu, sy, 16);
                if ((lane >> 2) == n8 && gp < N)
                    *(float2*)(out + gp * 64 + d0) = make_float2(sx, sy);
            }
        }
        sl ^= 1;
    }
}

extern "C" void kernel_launch(void* const* d_in, const int* in_sizes, int n_in,
                              void* d_out, int out_size)
{
    const float* pxyz  = (const float*)d_in[0];
    const float* pfeat = (const float*)d_in[1];
    const float* nxyz  = (const float*)d_in[2];
    const float* nfeat = (const float*)d_in[3];
    const float* Wphi  = (const float*)d_in[4];
    const float* bphi  = (const float*)d_in[5];
    const float* Wpsi  = (const float*)d_in[6];
    const float* bpsi  = (const float*)d_in[7];
    const float* Wal   = (const float*)d_in[8];
    const float* bal   = (const float*)d_in[9];
    const float* Wga   = (const float*)d_in[10];
    const float* bga   = (const float*)d_in[11];
    const float* Wd1   = (const float*)d_in[12];
    const float* bd1   = (const float*)d_in[13];
    const float* Wd2   = (const float*)d_in[14];
    const float* bd2   = (const float*)d_in[15];

    const int N = in_sizes[1] / DIM;

    int dev = 0;
    cudaGetDevice(&dev);
    int nsm = 148;
    cudaDeviceGetAttribute(&nsm, cudaDevAttrMultiProcessorCount, dev);

    cudaFuncSetAttribute(pt_main, cudaFuncAttributeMaxDynamicSharedMemorySize, SMEM_BYTES);

    const int ntiles = (N + 7) >> 3;
    const int grid = (ntiles < nsm) ? ntiles : nsm;
    pt_main<<<grid, THREADS, SMEM_BYTES>>>(pxyz, pfeat, nxyz, nfeat,
                                           Wphi, bphi, Wpsi, bpsi, Wal, bal,
                                           Wga, bga, Wd1, bd1, Wd2, bd2,
                                           (float*)d_out, N);
}